// round 3
// baseline (speedup 1.0000x reference)
#include <cuda_runtime.h>
#include <math.h>

// Problem constants
// B=2048, Z=512, N=128 nodes, M=127 conv outputs, channels 32->64->128->256->512

// Ping-pong scratch (device globals: allocation-free per harness rules)
__device__ float g_s1[2048L * 128 * 128];   // holds x0 (B*4096) and layer-1 out (B*128*128)
__device__ float g_s2[2048L * 256 * 128];   // holds layer-0 out (B*64*128) and layer-2 out (B*256*128)

__device__ __forceinline__ float mishf(float x) {
    float sp = (x > 20.f) ? x : log1pf(expf(x));
    return x * tanhf(sp);
}

// ---------------------------------------------------------------------------
// Kernel 1: x0 = mish(BN(trees @ W1^T + b1)), stored as (B, 4096) row-major
// (which IS the (B, 32, 128) layout channel-major).
// GEMM: M=2048, N=4096, K=512. Block tile 64x64, K-chunk 16, thread tile 4x4.
// ---------------------------------------------------------------------------
__global__ __launch_bounds__(256) void linear_bn_mish_kernel(
    const float* __restrict__ trees, const float* __restrict__ W1,
    const float* __restrict__ b1, const float* __restrict__ gamma,
    const float* __restrict__ beta, const float* __restrict__ rmean,
    const float* __restrict__ rvar, float* __restrict__ out)
{
    __shared__ float As[16][65];
    __shared__ float Bs[16][65];
    const int tid = threadIdx.x;
    const int tx = tid & 15, ty = tid >> 4;
    const int j0 = blockIdx.x * 64;  // output-feature tile
    const int i0 = blockIdx.y * 64;  // batch tile

    float acc[4][4] = {};

#pragma unroll 1
    for (int kt = 0; kt < 512; kt += 16) {
        for (int l = tid; l < 1024; l += 256) {
            int kk = l & 15, r = l >> 4;
            As[kk][r] = trees[(i0 + r) * 512 + kt + kk];
            Bs[kk][r] = W1[(j0 + r) * 512 + kt + kk];
        }
        __syncthreads();
#pragma unroll
        for (int kk = 0; kk < 16; kk++) {
            float a[4], w[4];
#pragma unroll
            for (int r = 0; r < 4; r++) a[r] = As[kk][ty * 4 + r];
#pragma unroll
            for (int r = 0; r < 4; r++) w[r] = Bs[kk][tx * 4 + r];
#pragma unroll
            for (int ri = 0; ri < 4; ri++)
#pragma unroll
                for (int rj = 0; rj < 4; rj++)
                    acc[ri][rj] = fmaf(a[ri], w[rj], acc[ri][rj]);
        }
        __syncthreads();
    }

#pragma unroll
    for (int ri = 0; ri < 4; ri++) {
        int i = i0 + ty * 4 + ri;
#pragma unroll
        for (int rj = 0; rj < 4; rj++) {
            int j = j0 + tx * 4 + rj;
            float v = acc[ri][rj] + b1[j];
            v = (v - rmean[j]) * rsqrtf(rvar[j] + 1e-5f) * gamma[j] + beta[j];
            out[(long)i * 4096 + j] = mishf(v);
        }
    }
}

// ---------------------------------------------------------------------------
// Conv layer: one CTA per sample. x (CIN x 128) resident in smem; gather
// G chunks (16 x 128) + W chunks (16 x 64) staged per K-chunk; fused
// TreeLayerNorm (ddof=1, zero node prepended) + mish via a second pass
// re-reading the just-written (L2-hot) output.
// ---------------------------------------------------------------------------
template <int CIN, int COUT>
__global__ __launch_bounds__(256) void tree_conv_kernel(
    const float* __restrict__ xin, const int* __restrict__ indexes,
    const float* __restrict__ cw, const float* __restrict__ cb,
    float* __restrict__ out)
{
    extern __shared__ float smem[];
    float* xs  = smem;                    // CIN*128
    float* Gs  = xs + CIN * 128;          // 16*128
    float* Ws  = Gs + 16 * 128;           // 16*68 (padded)
    float* red = Ws + 16 * 68;            // 20
    int*  idxs = (int*)(red + 20);        // 384

    constexpr int Ktot = 3 * CIN;
    const int b = blockIdx.x;
    const int tid = threadIdx.x;
    const int tx = tid & 15, ty = tid >> 4;

    for (int l = tid; l < CIN * 128; l += 256)
        xs[l] = xin[(long)b * CIN * 128 + l];
    for (int l = tid; l < 381; l += 256)
        idxs[l] = indexes[(long)b * 381 + l];
    if (tid == 0) { idxs[381] = 0; idxs[382] = 0; idxs[383] = 0; }
    __syncthreads();

    float lsum = 0.f, lsq = 0.f;

#pragma unroll 1
    for (int c0 = 0; c0 < COUT; c0 += 64) {
        float acc[4][8] = {};
#pragma unroll 1
        for (int k0 = 0; k0 < Ktot; k0 += 16) {
            __syncthreads();  // previous chunk's reads done before refill
            // Build gathered chunk: G[kc][m] = x[ci, idx[3m+kk]], k = k0+kc = ci*3+kk
            for (int l = tid; l < 16 * 128; l += 256) {
                int m = l & 127, kcl = l >> 7;
                int k = k0 + kcl;
                int ci = k / 3, kk = k - ci * 3;
                Gs[kcl * 128 + m] = (m < 127) ? xs[ci * 128 + idxs[m * 3 + kk]] : 0.f;
            }
            // W chunk (coalesced along K within a row of cw)
            for (int l = tid; l < 16 * 64; l += 256) {
                int kcl = l & 15, c = l >> 4;
                Ws[kcl * 68 + c] = cw[(long)(c0 + c) * Ktot + k0 + kcl];
            }
            __syncthreads();
#pragma unroll
            for (int kc = 0; kc < 16; kc++) {
                float a[8], w[4];
#pragma unroll
                for (int r = 0; r < 8; r++) a[r] = Gs[kc * 128 + tx + 16 * r];
#pragma unroll
                for (int q = 0; q < 4; q++) w[q] = Ws[kc * 68 + ty + 16 * q];
#pragma unroll
                for (int q = 0; q < 4; q++)
#pragma unroll
                    for (int r = 0; r < 8; r++)
                        acc[q][r] = fmaf(w[q], a[r], acc[q][r]);
            }
        }
        // Epilogue for this cout tile: bias, accumulate LN stats, store raw
#pragma unroll
        for (int q = 0; q < 4; q++) {
            int c = c0 + ty + 16 * q;
            float bias = cb[c];
#pragma unroll
            for (int r = 0; r < 8; r++) {
                int m = tx + 16 * r;
                if (m < 127) {
                    float v = acc[q][r] + bias;
                    lsum += v; lsq += v * v;
                    out[((long)b * COUT + c) * 128 + m + 1] = v;
                }
            }
        }
    }

    // CTA reduction for LayerNorm stats (zero node contributes 0, counts in n)
#pragma unroll
    for (int off = 16; off; off >>= 1) {
        lsum += __shfl_down_sync(0xFFFFFFFFu, lsum, off);
        lsq  += __shfl_down_sync(0xFFFFFFFFu, lsq, off);
    }
    int warp = tid >> 5, lane = tid & 31;
    if (lane == 0) { red[warp] = lsum; red[8 + warp] = lsq; }
    __syncthreads();
    if (tid == 0) {
        float s = 0.f, sq = 0.f;
        for (int w = 0; w < 8; w++) { s += red[w]; sq += red[8 + w]; }
        const float n = (float)(COUT * 128);
        float mean = s / n;
        float var = (sq - s * mean) / (n - 1.f);
        var = fmaxf(var, 0.f);
        red[16] = mean;
        red[17] = 1.f / (sqrtf(var) + 1e-5f);
    }
    __syncthreads();
    const float mean = red[16], inv = red[17];

    // Pass B: normalize + mish in place (reads are L2-hot). Node 0 handled
    // analytically: raw value is exactly 0.
    for (int l = tid; l < COUT * 128; l += 256) {
        int node = l & 127;
        float v = (node == 0) ? 0.f : out[(long)b * COUT * 128 + l];
        v = (v - mean) * inv;
        out[(long)b * COUT * 128 + l] = mishf(v);
    }
}

// ---------------------------------------------------------------------------
static inline int conv_smem_bytes(int cin) {
    return (cin * 128 + 16 * 128 + 16 * 68 + 20 + 384) * 4;
}

extern "C" void kernel_launch(void* const* d_in, const int* in_sizes, int n_in,
                              void* d_out, int out_size) {
    const float* trees   = (const float*)d_in[0];
    const int*   indexes = (const int*)d_in[1];
    const float* W1      = (const float*)d_in[2];
    const float* b1      = (const float*)d_in[3];
    const float* gamma   = (const float*)d_in[4];
    const float* beta    = (const float*)d_in[5];
    const float* rmean   = (const float*)d_in[6];
    const float* rvar    = (const float*)d_in[7];
    const float* cw0 = (const float*)d_in[8];
    const float* cb0 = (const float*)d_in[9];
    const float* cw1 = (const float*)d_in[10];
    const float* cb1 = (const float*)d_in[11];
    const float* cw2 = (const float*)d_in[12];
    const float* cb2 = (const float*)d_in[13];
    const float* cw3 = (const float*)d_in[14];
    const float* cb3 = (const float*)d_in[15];
    float* out = (float*)d_out;

    float *s1 = nullptr, *s2 = nullptr;
    cudaGetSymbolAddress((void**)&s1, g_s1);
    cudaGetSymbolAddress((void**)&s2, g_s2);

    cudaFuncSetAttribute(tree_conv_kernel<32, 64>,
                         cudaFuncAttributeMaxDynamicSharedMemorySize, conv_smem_bytes(32));
    cudaFuncSetAttribute(tree_conv_kernel<64, 128>,
                         cudaFuncAttributeMaxDynamicSharedMemorySize, conv_smem_bytes(64));
    cudaFuncSetAttribute(tree_conv_kernel<128, 256>,
                         cudaFuncAttributeMaxDynamicSharedMemorySize, conv_smem_bytes(128));
    cudaFuncSetAttribute(tree_conv_kernel<256, 512>,
                         cudaFuncAttributeMaxDynamicSharedMemorySize, conv_smem_bytes(256));

    // 1) Linear + BN + mish -> x0 in s1 (B x 4096 == B x 32 x 128)
    {
        dim3 grid(4096 / 64, 2048 / 64);
        linear_bn_mish_kernel<<<grid, 256>>>(trees, W1, b1, gamma, beta, rmean, rvar, s1);
    }
    // 2) Tree conv stack (each fuses conv + LayerNorm + mish)
    tree_conv_kernel<32, 64><<<2048, 256, conv_smem_bytes(32)>>>(s1, indexes, cw0, cb0, s2);
    tree_conv_kernel<64, 128><<<2048, 256, conv_smem_bytes(64)>>>(s2, indexes, cw1, cb1, s1);
    tree_conv_kernel<128, 256><<<2048, 256, conv_smem_bytes(128)>>>(s1, indexes, cw2, cb2, s2);
    tree_conv_kernel<256, 512><<<2048, 256, conv_smem_bytes(256)>>>(s2, indexes, cw3, cb3, out);
}

// round 5
// speedup vs baseline: 2.1280x; 2.1280x over previous
#include <cuda_runtime.h>
#include <cuda_bf16.h>
#include <math.h>
#include <stdint.h>

// ---------------------------------------------------------------------------
// B=2048, Z=512, N=128 nodes, M=127, channels 32->64->128->256->512
// Conv layers: warp-level mma.sync m16n8k16 bf16 (family-portable PTX),
// fp32 hi/lo 3-term split for accuracy. Fused bias + TreeLayerNorm + mish.
// ---------------------------------------------------------------------------

__device__ float    g_raw[2048L * 512 * 128];   // raw pre-LN scratch
__device__ uint32_t g_xa[2048L * 128 * 128];    // packed (bf16hi<<16)|bf16lo
__device__ uint32_t g_xb[2048L * 256 * 128];
__device__ uint16_t g_wh[522240];               // weight hi planes (all layers)
__device__ uint16_t g_wl[522240];               // weight lo planes
// plane offsets: L0:0 (64x96) L1:6144 (128x192) L2:30720 (256x384) L3:129024 (512x768)

__device__ __forceinline__ float mishf(float x) {
    float sp = (x > 20.f) ? x : log1pf(expf(x));
    return x * tanhf(sp);
}
__device__ __forceinline__ uint16_t bf16_bits(__nv_bfloat16 h) {
    uint16_t u; memcpy(&u, &h, 2); return u;
}
__device__ __forceinline__ uint32_t packf(float v) {
    __nv_bfloat16 h = __float2bfloat16(v);
    float r = v - __bfloat162float(h);
    __nv_bfloat16 l = __float2bfloat16(r);
    return ((uint32_t)bf16_bits(h) << 16) | (uint32_t)bf16_bits(l);
}
__device__ __forceinline__ uint32_t smem_u32(const void* p) {
    uint32_t a;
    asm("{ .reg .u64 t; cvta.to.shared.u64 t, %1; cvt.u32.u64 %0, t; }"
        : "=r"(a) : "l"(p));
    return a;
}

#define LDSM4(r0, r1, r2, r3, a) \
    asm volatile("ldmatrix.sync.aligned.m8n8.x4.shared.b16 {%0,%1,%2,%3}, [%4];" \
                 : "=r"(r0), "=r"(r1), "=r"(r2), "=r"(r3) : "r"(a))

__device__ __forceinline__ void mma_bf16(float* d, const uint32_t* a,
                                         const uint32_t* b) {
    asm volatile(
        "mma.sync.aligned.m16n8k16.row.col.f32.bf16.bf16.f32 "
        "{%0,%1,%2,%3}, {%4,%5,%6,%7}, {%8,%9}, {%0,%1,%2,%3};"
        : "+f"(d[0]), "+f"(d[1]), "+f"(d[2]), "+f"(d[3])
        : "r"(a[0]), "r"(a[1]), "r"(a[2]), "r"(a[3]), "r"(b[0]), "r"(b[1]));
}

// ---------------------------------------------------------------------------
// Weight prep: split fp32 -> bf16 hi/lo planes (row-major, same indexing)
// ---------------------------------------------------------------------------
__global__ void prep_w(const float* __restrict__ cw, int n,
                       uint16_t* __restrict__ wh, uint16_t* __restrict__ wl) {
    for (int i = blockIdx.x * blockDim.x + threadIdx.x; i < n;
         i += gridDim.x * blockDim.x) {
        float v = cw[i];
        __nv_bfloat16 h = __float2bfloat16(v);
        float r = v - __bfloat162float(h);
        wh[i] = bf16_bits(h);
        wl[i] = bf16_bits(__float2bfloat16(r));
    }
}

// ---------------------------------------------------------------------------
// Linear + BN + Mish -> packed x0 (B x 32 x 128)
// ---------------------------------------------------------------------------
__global__ __launch_bounds__(256) void linear_bn_mish_kernel(
    const float* __restrict__ trees, const float* __restrict__ W1,
    const float* __restrict__ b1, const float* __restrict__ gamma,
    const float* __restrict__ beta, const float* __restrict__ rmean,
    const float* __restrict__ rvar, uint32_t* __restrict__ out)
{
    __shared__ float As[16][65];
    __shared__ float Bs[16][65];
    const int tid = threadIdx.x;
    const int tx = tid & 15, ty = tid >> 4;
    const int j0 = blockIdx.x * 64;
    const int i0 = blockIdx.y * 64;

    float acc[4][4] = {};
#pragma unroll 1
    for (int kt = 0; kt < 512; kt += 16) {
        for (int l = tid; l < 1024; l += 256) {
            int kk = l & 15, r = l >> 4;
            As[kk][r] = trees[(i0 + r) * 512 + kt + kk];
            Bs[kk][r] = W1[(j0 + r) * 512 + kt + kk];
        }
        __syncthreads();
#pragma unroll
        for (int kk = 0; kk < 16; kk++) {
            float a[4], w[4];
#pragma unroll
            for (int r = 0; r < 4; r++) a[r] = As[kk][ty * 4 + r];
#pragma unroll
            for (int r = 0; r < 4; r++) w[r] = Bs[kk][tx * 4 + r];
#pragma unroll
            for (int ri = 0; ri < 4; ri++)
#pragma unroll
                for (int rj = 0; rj < 4; rj++)
                    acc[ri][rj] = fmaf(a[ri], w[rj], acc[ri][rj]);
        }
        __syncthreads();
    }
#pragma unroll
    for (int ri = 0; ri < 4; ri++) {
        int i = i0 + ty * 4 + ri;
#pragma unroll
        for (int rj = 0; rj < 4; rj++) {
            int j = j0 + tx * 4 + rj;
            float v = acc[ri][rj] + b1[j];
            v = (v - rmean[j]) * rsqrtf(rvar[j] + 1e-5f) * gamma[j] + beta[j];
            out[(long)i * 4096 + j] = packf(mishf(v));
        }
    }
}

// ---------------------------------------------------------------------------
// Conv layer: one CTA (256 thr) per sample.
//  O[o][n] = sum_k W[o][k] * G[k][n],  K = 3*CIN, via m16n8k16 bf16 MMA.
//  G staged transposed in smem as Gt[node][k] hi/lo (stride 72 halves = 144B).
//  3-term hi/lo split; fused bias + LN(ddof=1, zero node) + mish.
// ---------------------------------------------------------------------------
template <int CIN, int COUT, bool LAST>
__global__ __launch_bounds__(256) void conv_mma(
    const uint32_t* __restrict__ xp, const int* __restrict__ indexes,
    const float* __restrict__ cbias,
    const uint16_t* __restrict__ whg, const uint16_t* __restrict__ wlg,
    float* __restrict__ raw, void* __restrict__ outp)
{
    constexpr int KTOT  = 3 * CIN;
    constexpr int MT    = (COUT + 127) / 128;
    constexpr int CTA_M = (COUT < 128) ? COUT : 128;
    constexpr int WM    = CTA_M / 64;        // warp rows (1 or 2)
    constexpr int NW_N  = 8 / WM;            // warp cols (8 or 4)
    constexpr int WARP_N = 128 / NW_N;       // 16 or 32
    constexpr int NT    = WARP_N / 8;        // 2 or 4 n8-frags per warp

    extern __shared__ char smem[];
    int*      idxs = (int*)smem;                       // 384 ints
    float*    red  = (float*)(smem + 1536);            // 32 floats
    uint32_t* xs   = (uint32_t*)(smem + 1664);         // CIN*128
    uint16_t* Gh   = (uint16_t*)(smem + 1664 + CIN * 512);
    uint16_t* Gl   = Gh + 128 * 72;
    uint16_t* Wsh  = Gl + 128 * 72;
    uint16_t* Wsl  = Wsh + 128 * 72;

    const int b = blockIdx.x, tid = threadIdx.x;
    const int wid = tid >> 5, lane = tid & 31;
    const int warp_m = (wid / NW_N) * 64;
    const int warp_n = (wid % NW_N) * WARP_N;

    const uint32_t gh_b = smem_u32(Gh), gl_b = smem_u32(Gl);
    const uint32_t wh_b = smem_u32(Wsh), wl_b = smem_u32(Wsl);

    for (int i = tid; i < CIN * 128; i += 256) xs[i] = xp[(long)b * CIN * 128 + i];
    for (int i = tid; i < 381; i += 256) idxs[i] = indexes[(long)b * 381 + i];

    float lsum = 0.f, lsq = 0.f;

#pragma unroll 1
    for (int mt = 0; mt < MT; mt++) {
        float acc[4][NT][4];
#pragma unroll
        for (int a = 0; a < 4; a++)
#pragma unroll
            for (int c = 0; c < NT; c++)
#pragma unroll
                for (int e = 0; e < 4; e++) acc[a][c][e] = 0.f;

#pragma unroll 1
        for (int k0 = 0; k0 < KTOT; k0 += 64) {
            const int kc  = (KTOT - k0 < 64) ? (KTOT - k0) : 64;
            const int kc2 = kc >> 1;
            __syncthreads();   // previous chunk fully consumed
            // ---- stage gathered Gt (hi/lo), lanes vary over node ----
            for (int p = tid; p < 128 * kc2; p += 256) {
                int n  = p & 127;
                int jp = p >> 7;
                uint32_t v0 = 0, v1 = 0;
                if (n < 127) {
                    int k  = k0 + 2 * jp;
                    int i3 = n * 3;
                    int c0 = k / 3,  r0 = k - c0 * 3;
                    int c1 = (k + 1) / 3, r1 = (k + 1) - c1 * 3;
                    v0 = xs[c0 * 128 + idxs[i3 + r0]];
                    v1 = xs[c1 * 128 + idxs[i3 + r1]];
                }
                ((uint32_t*)Gh)[n * 36 + jp] = (v0 >> 16) | (v1 & 0xFFFF0000u);
                ((uint32_t*)Gl)[n * 36 + jp] = (v0 & 0xFFFFu) | (v1 << 16);
            }
            // ---- stage W chunk (coalesced u32 along k) ----
            for (int p = tid; p < CTA_M * kc2; p += 256) {
                int jp = p % kc2, o = p / kc2;
                long gi = ((long)(mt * 128 + o) * KTOT + k0) >> 1;
                ((uint32_t*)Wsh)[o * 36 + jp] = ((const uint32_t*)whg)[gi + jp];
                ((uint32_t*)Wsl)[o * 36 + jp] = ((const uint32_t*)wlg)[gi + jp];
            }
            __syncthreads();
            // ---- MMA over this chunk ----
            const int nks = kc >> 4;
#pragma unroll 1
            for (int s = 0; s < nks; s++) {
                const int ks = s * 16;
                uint32_t Bh[NT][2], Bl[NT][2];
                {
                    int brow = warp_n + (lane & 7) + ((lane & 16) ? 8 : 0);
                    int bcol = ks + ((lane & 8) ? 8 : 0);
#pragma unroll
                    for (int t2 = 0; t2 < NT / 2; t2++) {
                        uint32_t off = (uint32_t)(((brow + t2 * 16) * 72 + bcol) * 2);
                        LDSM4(Bh[2 * t2][0], Bh[2 * t2][1],
                              Bh[2 * t2 + 1][0], Bh[2 * t2 + 1][1], gh_b + off);
                        LDSM4(Bl[2 * t2][0], Bl[2 * t2][1],
                              Bl[2 * t2 + 1][0], Bl[2 * t2 + 1][1], gl_b + off);
                    }
                }
                int arow = warp_m + (lane & 15);
                int acol = ks + ((lane >> 4) << 3);
#pragma unroll
                for (int m16 = 0; m16 < 4; m16++) {
                    uint32_t Ah[4], Al[4];
                    uint32_t off = (uint32_t)(((arow + m16 * 16) * 72 + acol) * 2);
                    LDSM4(Ah[0], Ah[1], Ah[2], Ah[3], wh_b + off);
                    LDSM4(Al[0], Al[1], Al[2], Al[3], wl_b + off);
#pragma unroll
                    for (int nt = 0; nt < NT; nt++) {
                        mma_bf16(acc[m16][nt], Ah, Bh[nt]);
                        mma_bf16(acc[m16][nt], Ah, Bl[nt]);
                        mma_bf16(acc[m16][nt], Al, Bh[nt]);
                    }
                }
            }
        }
        // ---- epilogue for this out-tile: bias, LN stats, store raw ----
#pragma unroll
        for (int m16 = 0; m16 < 4; m16++) {
            int ml = warp_m + m16 * 16 + (lane >> 2);
            int o0 = mt * 128 + ml;
            float bias0 = cbias[o0], bias1 = cbias[o0 + 8];
#pragma unroll
            for (int nt = 0; nt < NT; nt++) {
                int n0 = warp_n + nt * 8 + 2 * (lane & 3);
                float v;
                v = acc[m16][nt][0] + bias0;
                { lsum += v; lsq += v * v;
                  raw[((long)b * COUT + o0) * 128 + n0 + 1] = v; }
                v = acc[m16][nt][2] + bias1;
                { lsum += v; lsq += v * v;
                  raw[((long)b * COUT + o0 + 8) * 128 + n0 + 1] = v; }
                if (n0 < 126) {
                    v = acc[m16][nt][1] + bias0;
                    lsum += v; lsq += v * v;
                    raw[((long)b * COUT + o0) * 128 + n0 + 2] = v;
                    v = acc[m16][nt][3] + bias1;
                    lsum += v; lsq += v * v;
                    raw[((long)b * COUT + o0 + 8) * 128 + n0 + 2] = v;
                }
            }
        }
    }

    // ---- CTA reduction for LN stats (zero node counts, contributes 0) ----
#pragma unroll
    for (int s = 16; s; s >>= 1) {
        lsum += __shfl_down_sync(0xFFFFFFFFu, lsum, s);
        lsq  += __shfl_down_sync(0xFFFFFFFFu, lsq, s);
    }
    if (lane == 0) { red[wid] = lsum; red[8 + wid] = lsq; }
    __syncthreads();
    if (tid == 0) {
        float s = 0.f, q = 0.f;
        for (int w = 0; w < 8; w++) { s += red[w]; q += red[8 + w]; }
        const float n = (float)(COUT * 128);
        float mean = s / n;
        float var = fmaxf((q - s * mean) / (n - 1.f), 0.f);
        red[16] = mean;
        red[17] = 1.f / (sqrtf(var) + 1e-5f);
    }
    __syncthreads();
    const float mean = red[16], inv = red[17];

    // ---- pass B: LN + mish (node0 raw is exactly 0) ----
    for (int l = tid; l < COUT * 128; l += 256) {
        int node = l & 127;
        float v = node ? raw[(long)b * COUT * 128 + l] : 0.f;
        v = mishf((v - mean) * inv);
        if (LAST) ((float*)outp)[(long)b * COUT * 128 + l] = v;
        else ((uint32_t*)outp)[(long)b * COUT * 128 + l] = packf(v);
    }
}

// ---------------------------------------------------------------------------
static inline int conv_smem(int cin) { return 1664 + cin * 512 + 4 * 18432; }

extern "C" void kernel_launch(void* const* d_in, const int* in_sizes, int n_in,
                              void* d_out, int out_size) {
    const float* trees   = (const float*)d_in[0];
    const int*   indexes = (const int*)d_in[1];
    const float* W1      = (const float*)d_in[2];
    const float* b1      = (const float*)d_in[3];
    const float* gamma   = (const float*)d_in[4];
    const float* beta    = (const float*)d_in[5];
    const float* rmean   = (const float*)d_in[6];
    const float* rvar    = (const float*)d_in[7];
    const float* cw0 = (const float*)d_in[8];
    const float* cb0 = (const float*)d_in[9];
    const float* cw1 = (const float*)d_in[10];
    const float* cb1 = (const float*)d_in[11];
    const float* cw2 = (const float*)d_in[12];
    const float* cb2 = (const float*)d_in[13];
    const float* cw3 = (const float*)d_in[14];
    const float* cb3 = (const float*)d_in[15];
    float* out = (float*)d_out;

    float* raw = nullptr; uint32_t *xa = nullptr, *xb = nullptr;
    uint16_t *wh = nullptr, *wl = nullptr;
    cudaGetSymbolAddress((void**)&raw, g_raw);
    cudaGetSymbolAddress((void**)&xa, g_xa);
    cudaGetSymbolAddress((void**)&xb, g_xb);
    cudaGetSymbolAddress((void**)&wh, g_wh);
    cudaGetSymbolAddress((void**)&wl, g_wl);

    cudaFuncSetAttribute(conv_mma<32, 64, false>,
        cudaFuncAttributeMaxDynamicSharedMemorySize, conv_smem(32));
    cudaFuncSetAttribute(conv_mma<64, 128, false>,
        cudaFuncAttributeMaxDynamicSharedMemorySize, conv_smem(64));
    cudaFuncSetAttribute(conv_mma<128, 256, false>,
        cudaFuncAttributeMaxDynamicSharedMemorySize, conv_smem(128));
    cudaFuncSetAttribute(conv_mma<256, 512, true>,
        cudaFuncAttributeMaxDynamicSharedMemorySize, conv_smem(256));

    // Weight hi/lo split (tiny, part of the graph)
    prep_w<<<64, 256>>>(cw0, 64 * 96,   wh + 0,      wl + 0);
    prep_w<<<64, 256>>>(cw1, 128 * 192, wh + 6144,   wl + 6144);
    prep_w<<<64, 256>>>(cw2, 256 * 384, wh + 30720,  wl + 30720);
    prep_w<<<64, 256>>>(cw3, 512 * 768, wh + 129024, wl + 129024);

    // Linear + BN + mish -> packed x0
    {
        dim3 grid(4096 / 64, 2048 / 64);
        linear_bn_mish_kernel<<<grid, 256>>>(trees, W1, b1, gamma, beta,
                                             rmean, rvar, xa);
    }
    // Conv stack
    conv_mma<32, 64, false><<<2048, 256, conv_smem(32)>>>(
        xa, indexes, cb0, wh + 0, wl + 0, raw, xb);
    conv_mma<64, 128, false><<<2048, 256, conv_smem(64)>>>(
        xb, indexes, cb1, wh + 6144, wl + 6144, raw, xa);
    conv_mma<128, 256, false><<<2048, 256, conv_smem(128)>>>(
        xa, indexes, cb2, wh + 30720, wl + 30720, raw, xb);
    conv_mma<256, 512, true><<<2048, 256, conv_smem(256)>>>(
        xb, indexes, cb3, wh + 129024, wl + 129024, raw, out);
}

// round 14
// speedup vs baseline: 2.1396x; 1.0055x over previous
#include <cuda_runtime.h>
#include <cuda_bf16.h>
#include <math.h>
#include <stdint.h>

// ---------------------------------------------------------------------------
// B=2048, Z=512, N=128 nodes, M=127, channels 32->64->128->256->512
// Conv layers: warp-level mma.sync m16n8k16 bf16, fp32 hi/lo 3-term split.
// Double-buffered K-chunk-32 pipeline, one __syncthreads per chunk.
// ---------------------------------------------------------------------------

__device__ float    g_raw[2048L * 512 * 128];   // raw pre-LN scratch
__device__ uint32_t g_xa[2048L * 128 * 128];    // packed (bf16hi<<16)|bf16lo
__device__ uint32_t g_xb[2048L * 256 * 128];
__device__ uint16_t g_wh[522240];               // weight hi planes (all layers)
__device__ uint16_t g_wl[522240];               // weight lo planes
// plane offsets: L0:0 (64x96) L1:6144 (128x192) L2:30720 (256x384) L3:129024 (512x768)

__device__ __forceinline__ float mishf(float x) {
    float sp = (x > 20.f) ? x : log1pf(expf(x));
    return x * tanhf(sp);
}
__device__ __forceinline__ uint16_t bf16_bits(__nv_bfloat16 h) {
    uint16_t u; memcpy(&u, &h, 2); return u;
}
__device__ __forceinline__ uint32_t packf(float v) {
    __nv_bfloat16 h = __float2bfloat16(v);
    float r = v - __bfloat162float(h);
    __nv_bfloat16 l = __float2bfloat16(r);
    return ((uint32_t)bf16_bits(h) << 16) | (uint32_t)bf16_bits(l);
}
__device__ __forceinline__ uint32_t smem_u32(const void* p) {
    uint32_t a;
    asm("{ .reg .u64 t; cvta.to.shared.u64 t, %1; cvt.u32.u64 %0, t; }"
        : "=r"(a) : "l"(p));
    return a;
}

#define LDSM4(r0, r1, r2, r3, a) \
    asm volatile("ldmatrix.sync.aligned.m8n8.x4.shared.b16 {%0,%1,%2,%3}, [%4];" \
                 : "=r"(r0), "=r"(r1), "=r"(r2), "=r"(r3) : "r"(a))

__device__ __forceinline__ void mma_bf16(float* d, const uint32_t* a,
                                         const uint32_t* b) {
    asm volatile(
        "mma.sync.aligned.m16n8k16.row.col.f32.bf16.bf16.f32 "
        "{%0,%1,%2,%3}, {%4,%5,%6,%7}, {%8,%9}, {%0,%1,%2,%3};"
        : "+f"(d[0]), "+f"(d[1]), "+f"(d[2]), "+f"(d[3])
        : "r"(a[0]), "r"(a[1]), "r"(a[2]), "r"(a[3]), "r"(b[0]), "r"(b[1]));
}

// ---------------------------------------------------------------------------
// Weight prep (all 4 layers, one launch): fp32 -> bf16 hi/lo planes
// ---------------------------------------------------------------------------
__global__ void prep_all(const float* __restrict__ w0, const float* __restrict__ w1,
                         const float* __restrict__ w2, const float* __restrict__ w3,
                         uint16_t* __restrict__ wh, uint16_t* __restrict__ wl) {
    for (int i = blockIdx.x * blockDim.x + threadIdx.x; i < 522240;
         i += gridDim.x * blockDim.x) {
        float v;
        if (i < 6144)        v = w0[i];
        else if (i < 30720)  v = w1[i - 6144];
        else if (i < 129024) v = w2[i - 30720];
        else                 v = w3[i - 129024];
        __nv_bfloat16 h = __float2bfloat16(v);
        float r = v - __bfloat162float(h);
        wh[i] = bf16_bits(h);
        wl[i] = bf16_bits(__float2bfloat16(r));
    }
}

// ---------------------------------------------------------------------------
// Linear + BN + Mish -> packed x0 (B x 32 x 128)
// ---------------------------------------------------------------------------
__global__ __launch_bounds__(256) void linear_bn_mish_kernel(
    const float* __restrict__ trees, const float* __restrict__ W1,
    const float* __restrict__ b1, const float* __restrict__ gamma,
    const float* __restrict__ beta, const float* __restrict__ rmean,
    const float* __restrict__ rvar, uint32_t* __restrict__ out)
{
    __shared__ float As[16][65];
    __shared__ float Bs[16][65];
    const int tid = threadIdx.x;
    const int tx = tid & 15, ty = tid >> 4;
    const int j0 = blockIdx.x * 64;
    const int i0 = blockIdx.y * 64;

    float acc[4][4] = {};
#pragma unroll 1
    for (int kt = 0; kt < 512; kt += 16) {
        for (int l = tid; l < 1024; l += 256) {
            int kk = l & 15, r = l >> 4;
            As[kk][r] = trees[(i0 + r) * 512 + kt + kk];
            Bs[kk][r] = W1[(j0 + r) * 512 + kt + kk];
        }
        __syncthreads();
#pragma unroll
        for (int kk = 0; kk < 16; kk++) {
            float a[4], w[4];
#pragma unroll
            for (int r = 0; r < 4; r++) a[r] = As[kk][ty * 4 + r];
#pragma unroll
            for (int r = 0; r < 4; r++) w[r] = Bs[kk][tx * 4 + r];
#pragma unroll
            for (int ri = 0; ri < 4; ri++)
#pragma unroll
                for (int rj = 0; rj < 4; rj++)
                    acc[ri][rj] = fmaf(a[ri], w[rj], acc[ri][rj]);
        }
        __syncthreads();
    }
#pragma unroll
    for (int ri = 0; ri < 4; ri++) {
        int i = i0 + ty * 4 + ri;
#pragma unroll
        for (int rj = 0; rj < 4; rj++) {
            int j = j0 + tx * 4 + rj;
            float v = acc[ri][rj] + b1[j];
            v = (v - rmean[j]) * rsqrtf(rvar[j] + 1e-5f) * gamma[j] + beta[j];
            out[(long)i * 4096 + j] = packf(mishf(v));
        }
    }
}

// ---------------------------------------------------------------------------
// Conv layer: one CTA (256 thr) per sample. m16n8k16 bf16 MMA, hi/lo 3-term.
// Double-buffered K-chunk-32 staging, one sync per chunk. Fused bias+LN+mish.
// Staged planes: 128 rows x 40 halves (80B stride, ldmatrix-safe).
// ---------------------------------------------------------------------------
template <int CIN, int COUT, bool LAST>
__global__ __launch_bounds__(256) void conv_mma(
    const uint32_t* __restrict__ xp, const int* __restrict__ indexes,
    const float* __restrict__ cbias,
    const uint16_t* __restrict__ whg, const uint16_t* __restrict__ wlg,
    float* __restrict__ raw, void* __restrict__ outp)
{
    constexpr int KTOT  = 3 * CIN;
    constexpr int NCH   = KTOT / 32;         // K-chunks of 32
    constexpr int MT    = (COUT + 127) / 128;
    constexpr int CTA_M = (COUT < 128) ? COUT : 128;
    constexpr int WM    = CTA_M / 64;        // warp rows (1 or 2)
    constexpr int NW_N  = 8 / WM;            // warp cols (8 or 4)
    constexpr int WARP_N = 128 / NW_N;       // 16 or 32
    constexpr int NT    = WARP_N / 8;        // n8-frags per warp

    constexpr int PLANE_U32 = 128 * 20;      // 128 rows x 20 u32 (40 halves)
    constexpr int BUF_U32   = 4 * PLANE_U32; // Gh,Gl,Wh,Wl

    extern __shared__ char smem[];
    int*      idxs = (int*)smem;                       // 384 ints
    float*    red  = (float*)(smem + 1536);            // 32 floats
    uint32_t* xs   = (uint32_t*)(smem + 1664);         // CIN*128
    uint32_t* stg  = (uint32_t*)(smem + 1664 + CIN * 512);  // 2 bufs x 4 planes

    const int b = blockIdx.x, tid = threadIdx.x;
    const int wid = tid >> 5, lane = tid & 31;
    const int warp_m = (wid / NW_N) * 64;
    const int warp_n = (wid % NW_N) * WARP_N;
    const uint32_t stg_b = smem_u32(stg);

    for (int i = tid; i < CIN * 128; i += 256) xs[i] = xp[(long)b * CIN * 128 + i];
    for (int i = tid; i < 381; i += 256) idxs[i] = indexes[(long)b * 381 + i];

    float lsum = 0.f, lsq = 0.f;

#pragma unroll 1
    for (int mt = 0; mt < MT; mt++) {
        float acc[4][NT][4];
#pragma unroll
        for (int a = 0; a < 4; a++)
#pragma unroll
            for (int c = 0; c < NT; c++)
#pragma unroll
                for (int e = 0; e < 4; e++) acc[a][c][e] = 0.f;

        auto stage = [&](int bf, int k0) {
            uint32_t* Gh = stg + bf * BUF_U32;
            uint32_t* Gl = Gh + PLANE_U32;
            uint32_t* Wh = Gl + PLANE_U32;
            uint32_t* Wl = Wh + PLANE_U32;
            // gathered G: 128 nodes x 16 u32 (2 k each)
            {
                int n  = tid & 127;
                int jp0 = (tid >> 7) * 8;          // 8 u32 per thread
                uint32_t vh[8], vl[8];
                if (n < 127) {
                    int i3 = n * 3;
                    int ia = idxs[i3], ib2 = idxs[i3 + 1], ic = idxs[i3 + 2];
#pragma unroll
                    for (int e = 0; e < 8; e++) {
                        int k = k0 + 2 * (jp0 + e);
                        int c0 = k / 3, r0 = k - c0 * 3;
                        int c1 = (k + 1) / 3, r1 = (k + 1) - c1 * 3;
                        uint32_t v0 = xs[c0 * 128 + (r0 == 0 ? ia : r0 == 1 ? ib2 : ic)];
                        uint32_t v1 = xs[c1 * 128 + (r1 == 0 ? ia : r1 == 1 ? ib2 : ic)];
                        vh[e] = (v0 >> 16) | (v1 & 0xFFFF0000u);
                        vl[e] = (v0 & 0xFFFFu) | (v1 << 16);
                    }
                } else {
#pragma unroll
                    for (int e = 0; e < 8; e++) { vh[e] = 0; vl[e] = 0; }
                }
#pragma unroll
                for (int e = 0; e < 8; e++) {
                    Gh[n * 20 + jp0 + e] = vh[e];
                    Gl[n * 20 + jp0 + e] = vl[e];
                }
            }
            // W chunk: CTA_M rows x 16 u32
            for (int p = tid; p < CTA_M * 16; p += 256) {
                int jp = p & 15, o = p >> 4;
                long gi = (((long)(mt * 128 + o) * KTOT + k0) >> 1) + jp;
                Wh[o * 20 + jp] = ((const uint32_t*)whg)[gi];
                Wl[o * 20 + jp] = ((const uint32_t*)wlg)[gi];
            }
        };

        __syncthreads();          // xs/idxs ready (mt=0) / prev bufs free
        stage(0, 0);
        __syncthreads();

#pragma unroll 1
        for (int c = 0; c < NCH; c++) {
            if (c + 1 < NCH) stage((c + 1) & 1, (c + 1) * 32);
            // ---- MMA on buffer c&1 ----
            const uint32_t base = stg_b + (uint32_t)((c & 1) * BUF_U32 * 4);
            const uint32_t gh_b = base;
            const uint32_t gl_b = base + PLANE_U32 * 4;
            const uint32_t wh_b = base + PLANE_U32 * 8;
            const uint32_t wl_b = base + PLANE_U32 * 12;
#pragma unroll
            for (int s = 0; s < 2; s++) {
                const int ks = s * 16;
                uint32_t Bh[NT][2], Bl[NT][2];
                {
                    int brow = warp_n + (lane & 7) + ((lane & 16) ? 8 : 0);
                    int bcol = ks + ((lane & 8) ? 8 : 0);
#pragma unroll
                    for (int t2 = 0; t2 < NT / 2; t2++) {
                        uint32_t off = (uint32_t)(((brow + t2 * 16) * 40 + bcol) * 2);
                        LDSM4(Bh[2 * t2][0], Bh[2 * t2][1],
                              Bh[2 * t2 + 1][0], Bh[2 * t2 + 1][1], gh_b + off);
                        LDSM4(Bl[2 * t2][0], Bl[2 * t2][1],
                              Bl[2 * t2 + 1][0], Bl[2 * t2 + 1][1], gl_b + off);
                    }
                }
                int arow = warp_m + (lane & 15);
                int acol = ks + ((lane >> 4) << 3);
#pragma unroll
                for (int m16 = 0; m16 < 4; m16++) {
                    uint32_t Ah[4], Al[4];
                    uint32_t off = (uint32_t)(((arow + m16 * 16) * 40 + acol) * 2);
                    LDSM4(Ah[0], Ah[1], Ah[2], Ah[3], wh_b + off);
                    LDSM4(Al[0], Al[1], Al[2], Al[3], wl_b + off);
#pragma unroll
                    for (int nt = 0; nt < NT; nt++) {
                        mma_bf16(acc[m16][nt], Ah, Bh[nt]);
                        mma_bf16(acc[m16][nt], Ah, Bl[nt]);
                        mma_bf16(acc[m16][nt], Al, Bh[nt]);
                    }
                }
            }
            __syncthreads();
        }

        // ---- epilogue: bias, LN stats, store raw ----
#pragma unroll
        for (int m16 = 0; m16 < 4; m16++) {
            int ml = warp_m + m16 * 16 + (lane >> 2);
            int o0 = mt * 128 + ml;
            float bias0 = cbias[o0], bias1 = cbias[o0 + 8];
#pragma unroll
            for (int nt = 0; nt < NT; nt++) {
                int n0 = warp_n + nt * 8 + 2 * (lane & 3);
                float v;
                v = acc[m16][nt][0] + bias0;
                { lsum += v; lsq += v * v;
                  raw[((long)b * COUT + o0) * 128 + n0 + 1] = v; }
                v = acc[m16][nt][2] + bias1;
                { lsum += v; lsq += v * v;
                  raw[((long)b * COUT + o0 + 8) * 128 + n0 + 1] = v; }
                if (n0 < 126) {
                    v = acc[m16][nt][1] + bias0;
                    lsum += v; lsq += v * v;
                    raw[((long)b * COUT + o0) * 128 + n0 + 2] = v;
                    v = acc[m16][nt][3] + bias1;
                    lsum += v; lsq += v * v;
                    raw[((long)b * COUT + o0 + 8) * 128 + n0 + 2] = v;
                }
            }
        }
    }

    // ---- CTA reduction for LN stats ----
#pragma unroll
    for (int s = 16; s; s >>= 1) {
        lsum += __shfl_down_sync(0xFFFFFFFFu, lsum, s);
        lsq  += __shfl_down_sync(0xFFFFFFFFu, lsq, s);
    }
    if (lane == 0) { red[wid] = lsum; red[8 + wid] = lsq; }
    __syncthreads();
    if (tid == 0) {
        float s = 0.f, q = 0.f;
        for (int w = 0; w < 8; w++) { s += red[w]; q += red[8 + w]; }
        const float n = (float)(COUT * 128);
        float mean = s / n;
        float var = fmaxf((q - s * mean) / (n - 1.f), 0.f);
        red[16] = mean;
        red[17] = 1.f / (sqrtf(var) + 1e-5f);
    }
    __syncthreads();
    const float mean = red[16], inv = red[17];

    // ---- pass B: LN + mish (node0 raw is exactly 0; L2-hot reads) ----
    for (int l = tid; l < COUT * 128; l += 256) {
        int node = l & 127;
        float v = node ? raw[(long)b * COUT * 128 + l] : 0.f;
        v = mishf((v - mean) * inv);
        if (LAST) ((float*)outp)[(long)b * COUT * 128 + l] = v;
        else ((uint32_t*)outp)[(long)b * COUT * 128 + l] = packf(v);
    }
}

// ---------------------------------------------------------------------------
static inline int conv_smem(int cin) { return 1664 + cin * 512 + 81920; }

extern "C" void kernel_launch(void* const* d_in, const int* in_sizes, int n_in,
                              void* d_out, int out_size) {
    const float* trees   = (const float*)d_in[0];
    const int*   indexes = (const int*)d_in[1];
    const float* W1      = (const float*)d_in[2];
    const float* b1      = (const float*)d_in[3];
    const float* gamma   = (const float*)d_in[4];
    const float* beta    = (const float*)d_in[5];
    const float* rmean   = (const float*)d_in[6];
    const float* rvar    = (const float*)d_in[7];
    const float* cw0 = (const float*)d_in[8];
    const float* cb0 = (const float*)d_in[9];
    const float* cw1 = (const float*)d_in[10];
    const float* cb1 = (const float*)d_in[11];
    const float* cw2 = (const float*)d_in[12];
    const float* cb2 = (const float*)d_in[13];
    const float* cw3 = (const float*)d_in[14];
    const float* cb3 = (const float*)d_in[15];
    float* out = (float*)d_out;

    float* raw = nullptr; uint32_t *xa = nullptr, *xb = nullptr;
    uint16_t *wh = nullptr, *wl = nullptr;
    cudaGetSymbolAddress((void**)&raw, g_raw);
    cudaGetSymbolAddress((void**)&xa, g_xa);
    cudaGetSymbolAddress((void**)&xb, g_xb);
    cudaGetSymbolAddress((void**)&wh, g_wh);
    cudaGetSymbolAddress((void**)&wl, g_wl);

    cudaFuncSetAttribute(conv_mma<32, 64, false>,
        cudaFuncAttributeMaxDynamicSharedMemorySize, conv_smem(32));
    cudaFuncSetAttribute(conv_mma<64, 128, false>,
        cudaFuncAttributeMaxDynamicSharedMemorySize, conv_smem(64));
    cudaFuncSetAttribute(conv_mma<128, 256, false>,
        cudaFuncAttributeMaxDynamicSharedMemorySize, conv_smem(128));
    cudaFuncSetAttribute(conv_mma<256, 512, true>,
        cudaFuncAttributeMaxDynamicSharedMemorySize, conv_smem(256));

    // 0) weight hi/lo split (single launch)
    prep_all<<<512, 256>>>(cw0, cw1, cw2, cw3, wh, wl);
    // 1) linear + BN + mish -> packed x0
    {
        dim3 grid(4096 / 64, 2048 / 64);
        linear_bn_mish_kernel<<<grid, 256>>>(trees, W1, b1, gamma, beta,
                                             rmean, rvar, xa);
    }
    // 2-5) conv stack
    conv_mma<32, 64, false><<<2048, 256, conv_smem(32)>>>(
        xa, indexes, cb0, wh + 0, wl + 0, raw, xb);
    conv_mma<64, 128, false><<<2048, 256, conv_smem(64)>>>(
        xb, indexes, cb1, wh + 6144, wl + 6144, raw, xa);
    conv_mma<128, 256, false><<<2048, 256, conv_smem(128)>>>(
        xa, indexes, cb2, wh + 30720, wl + 30720, raw, xb);
    conv_mma<256, 512, true><<<2048, 256, conv_smem(256)>>>(
        xb, indexes, cb3, wh + 129024, wl + 129024, raw, out);
}